// round 3
// baseline (speedup 1.0000x reference)
#include <cuda_runtime.h>
#include <cuda_bf16.h>
#include <math.h>

#define H_DIM 1000
#define W_DIM 1000
#define NVERT 20
#define ROWS_PB 4                 // rows per block
#define TPR 125                   // threads per row
#define PX 8                      // pixels per thread
#define BLOCK (ROWS_PB * TPR)     // 500
#define GRID (H_DIM / ROWS_PB)    // 250

__global__ void __launch_bounds__(512, 2)
render_kernel(const float* __restrict__ vpos,
              const float* __restrict__ vcol,
              const float* __restrict__ vrad,
              const float* __restrict__ cpos,
              const float* __restrict__ crot,
              const float* __restrict__ fl,
              const float* __restrict__ bg,
              float* __restrict__ out)
{
    __shared__ float4 sp[NVERT * 2];   // [xn, yn, r2, E], [E*cr, E*cg, E*cb, 0]
    __shared__ unsigned smask[ROWS_PB];

    const int t = threadIdx.x;
    const int row_base = blockIdx.x * ROWS_PB;

    if (t < 32) {
        bool c0 = false, c1 = false, c2 = false, c3 = false;
        if (t < NVERT) {
            float px = vpos[3*t+0], py = vpos[3*t+1], pz = vpos[3*t+2];
            float x = fmaf(px, crot[0], fmaf(py, crot[3], fmaf(pz, crot[6], cpos[0])));
            float y = fmaf(px, crot[1], fmaf(py, crot[4], fmaf(pz, crot[7], cpos[1])));
            float z = fmaf(px, crot[2], fmaf(py, crot[5], fmaf(pz, crot[8], cpos[2])));
            float f    = fl[0];
            float invz = __fdividef(1.0f, z);
            float xn = f * x * invz;
            float yn = f * y * invz;
            float rn = f * vrad[t] * invz;
            float r2 = rn * rn;
            bool in_depth = (z > 1.0f) && (z < 45.0f);
            float closeness = fminf(fmaxf((45.0f - z) * (1.0f / 44.0f), 0.0f), 1.0f);
            float E = in_depth ? __expf(closeness * 10.0f) : 0.0f;  // bg logit 0 -> e^0=1
            sp[2*t]   = make_float4(xn, yn, r2, E);
            sp[2*t+1] = make_float4(E * vcol[3*t+0], E * vcol[3*t+1], E * vcol[3*t+2], 0.0f);
            bool live = (E > 0.0f);
            float gy0 = 1.0f - (2.0f * (row_base + 0) + 1.0f) * (1.0f / H_DIM);
            float gy1 = 1.0f - (2.0f * (row_base + 1) + 1.0f) * (1.0f / H_DIM);
            float gy2 = 1.0f - (2.0f * (row_base + 2) + 1.0f) * (1.0f / H_DIM);
            float gy3 = 1.0f - (2.0f * (row_base + 3) + 1.0f) * (1.0f / H_DIM);
            float d0 = gy0 - yn, d1 = gy1 - yn, d2 = gy2 - yn, d3 = gy3 - yn;
            c0 = live && (d0 * d0 <= r2);
            c1 = live && (d1 * d1 <= r2);
            c2 = live && (d2 * d2 <= r2);
            c3 = live && (d3 * d3 <= r2);
        }
        unsigned m0 = __ballot_sync(0xffffffffu, c0);
        unsigned m1 = __ballot_sync(0xffffffffu, c1);
        unsigned m2 = __ballot_sync(0xffffffffu, c2);
        unsigned m3 = __ballot_sync(0xffffffffu, c3);
        if (t == 0) { smask[0] = m0; smask[1] = m1; smask[2] = m2; smask[3] = m3; }
    }
    __syncthreads();

    const int rl  = t / TPR;                 // 0..3
    const int ci  = t - rl * TPR;            // 0..124
    const int row = row_base + rl;
    const int x0  = ci * PX;

    const float gy  = 1.0f - (2.0f * row + 1.0f) * (1.0f / H_DIM);
    const float dgx = -2.0f / W_DIM;
    const float gx0 = 1.0f - (2.0f * x0 + 1.0f) * (1.0f / W_DIM);

    const float bgr = bg[0], bgg = bg[1], bgb = bg[2];
    float s[PX], cr[PX], cg[PX], cb[PX];
#pragma unroll
    for (int j = 0; j < PX; j++) { s[j] = 1.0f; cr[j] = bgr; cg[j] = bgg; cb[j] = bgb; }

    unsigned mask = smask[rl];
    while (mask) {
        int i = __ffs(mask) - 1;
        mask &= mask - 1;
        float4 a = sp[2*i];       // xn, yn, r2, E
        float4 c = sp[2*i+1];     // E*cr, E*cg, E*cb
        float dy  = gy - a.y;
        float dy2 = dy * dy;
        float dx  = gx0 - a.x;
#pragma unroll
        for (int j = 0; j < PX; j++) {
            float d = fmaf(dx, dx, dy2);
            if (d <= a.z) { s[j] += a.w; cr[j] += c.x; cg[j] += c.y; cb[j] += c.z; }
            dx += dgx;
        }
    }

    float o[PX * 3];
#pragma unroll
    for (int j = 0; j < PX; j++) {
        float inv = __fdividef(1.0f, s[j]);
        o[3*j+0] = cr[j] * inv;
        o[3*j+1] = cg[j] * inv;
        o[3*j+2] = cb[j] * inv;
    }

    // 8 px * 3 ch = 24 floats = 6 float4, contiguous per thread
    float4* out4 = reinterpret_cast<float4*>(out) + (size_t)row * (W_DIM * 3 / 4) + ci * 6;
#pragma unroll
    for (int k = 0; k < 6; k++) {
        out4[k] = make_float4(o[4*k+0], o[4*k+1], o[4*k+2], o[4*k+3]);
    }
}

extern "C" void kernel_launch(void* const* d_in, const int* in_sizes, int n_in,
                              void* d_out, int out_size)
{
    const float* vert_pos = (const float*)d_in[0];
    const float* vert_col = (const float*)d_in[1];
    const float* vert_rad = (const float*)d_in[2];
    const float* cam_pos  = (const float*)d_in[3];
    const float* cam_rot  = (const float*)d_in[4];
    const float* focal    = (const float*)d_in[5];
    const float* bg_col   = (const float*)d_in[6];
    float* out = (float*)d_out;

    render_kernel<<<GRID, BLOCK>>>(vert_pos, vert_col, vert_rad,
                                   cam_pos, cam_rot, focal, bg_col, out);
}